// round 8
// baseline (speedup 1.0000x reference)
#include <cuda_runtime.h>
#include <math.h>

// Problem constants
#define BATCH 8
#define NNODES 4096
#define DIN0 64
#define DHID 128
#define DOUT0 64
#define CAP 512          // max neighbors per row (mean ~82 at 2% density; P(>512)~0)

// ---------------- static device scratch (no allocations allowed) -------------
__device__ int   d_col[NNODES * CAP];            // 8 MB
__device__ int   d_deg[NNODES];
__device__ float d_h1[BATCH * NNODES * DHID];    // 16 MB (aliased for h2)
__device__ float d_t1[BATCH * NNODES * DHID];    // 16 MB
__device__ float d_wt1[DIN0 * DHID];             // W1^T  [k][c]
__device__ float d_wt2[DHID * DOUT0];            // W2^T  [k][c]

// ---------------- transpose W1, W2 into k-major layout -----------------------
__global__ void prep_kernel(const float* __restrict__ W1, const float* __restrict__ W2) {
    int i = blockIdx.x * blockDim.x + threadIdx.x;
    if (i < DHID * DIN0) {            // W1: [128][64] -> wt1[k*128 + c]
        int c = i / DIN0, k = i % DIN0;
        d_wt1[k * DHID + c] = W1[i];
    }
    if (i < DOUT0 * DHID) {           // W2: [64][128] -> wt2[k*64 + c]
        int c = i / DHID, k = i % DHID;
        d_wt2[k * DOUT0 + c] = W2[i];
    }
}

// ---------------- build CSR from dense binary graph (order-preserving) -------
__global__ void build_csr_kernel(const float* __restrict__ graph) {
    int row  = blockIdx.x * (blockDim.x >> 5) + (threadIdx.x >> 5);
    int lane = threadIdx.x & 31;
    if (row >= NNODES) return;
    const float* g = graph + (size_t)row * NNODES;
    int cnt = 0;
    for (int base = 0; base < NNODES; base += 32) {
        float v = g[base + lane];
        unsigned ball = __ballot_sync(0xffffffffu, v != 0.0f);
        int prefix = __popc(ball & ((1u << lane) - 1u));
        if (v != 0.0f) {
            int pos = cnt + prefix;
            if (pos < CAP) d_col[row * CAP + pos] = base + lane;
        }
        cnt += __popc(ball);
    }
    if (lane == 0) d_deg[row] = (cnt < CAP) ? cnt : CAP;
}

// ---------------- linear body: out[r][c] = sum_k x[r][k] * Wt[k][c] ----------
template <int DIN, int DOUT>
__device__ __forceinline__ void lin_body(const float* __restrict__ x,
                                         const float* __restrict__ wt,
                                         float* __restrict__ out) {
    constexpr int RPB = 32;
    __shared__ float xs[RPB * DIN];
    long base = (long)blockIdx.x * RPB;
    const float4* xg  = (const float4*)(x + base * DIN);
    float4*       xs4 = (float4*)xs;
    for (int i = threadIdx.x; i < RPB * DIN / 4; i += blockDim.x) xs4[i] = xg[i];
    __syncthreads();

    int c = threadIdx.x;   // blockDim == DOUT
    float acc[RPB];
#pragma unroll
    for (int r = 0; r < RPB; r++) acc[r] = 0.0f;

    for (int k = 0; k < DIN; k += 4) {
        float w0 = wt[(k + 0) * DOUT + c];
        float w1 = wt[(k + 1) * DOUT + c];
        float w2 = wt[(k + 2) * DOUT + c];
        float w3 = wt[(k + 3) * DOUT + c];
#pragma unroll
        for (int r = 0; r < RPB; r++) {
            float4 xv = *(const float4*)&xs[r * DIN + k];
            acc[r] = fmaf(xv.x, w0, fmaf(xv.y, w1, fmaf(xv.z, w2, fmaf(xv.w, w3, acc[r]))));
        }
    }
#pragma unroll
    for (int r = 0; r < RPB; r++) out[(base + r) * DOUT + c] = acc[r];
}

__global__ void lin1_kernel(const float* __restrict__ x) {
    lin_body<DIN0, DHID>(x, d_wt1, d_h1);
}
__global__ void lin2_kernel() {
    lin_body<DHID, DOUT0>(d_t1, d_wt2, d_h1);   // h2 aliases d_h1
}

// ---------------- sparse GAT aggregation: warp = 2 independent 16-lane engines
// Each 16-lane group runs an online softmax over a strided half of the CSR
// neighbor list (group g handles quads starting at 4g, stride 8), with a
// merged 4-way in-group reduction (9 SHFLs / 4 neighbors, both groups in
// lockstep => 9 SHFL issues / 8 neighbors). States merged at the end via the
// standard flash combine. No tail loop: invalid slots get score -inf.
template <int D, bool RELU>
__device__ __forceinline__ void agg_body(const float* __restrict__ h,
                                         const float* __restrict__ bias,
                                         float* __restrict__ out) {
    constexpr int VEC = D / 16;                  // 8 (agg1) or 4 (agg2)
    const unsigned FULL = 0xffffffffu;
    int warp  = threadIdx.x >> 5;
    int lane  = threadIdx.x & 31;
    int k     = lane & 15;                       // lane within group
    int grp   = lane >> 4;                       // 0 or 1
    int gbase = lane & 16;
    unsigned gmask = 0xFFFFu << gbase;

    long row = (long)blockIdx.x * (blockDim.x >> 5) + warp;   // row in [0, B*N)
    if (row >= (long)BATCH * NNODES) return;
    int n = (int)(row & (NNODES - 1));
    const float* hb = h + (size_t)(row - n) * D;   // batch base

    // this row's features: dims [k*VEC, k*VEC+VEC)
    float f[VEC];
#pragma unroll
    for (int v = 0; v < VEC; v += 4) {
        float4 t = *(const float4*)(hb + (size_t)n * D + k * VEC + v);
        f[v] = t.x; f[v + 1] = t.y; f[v + 2] = t.z; f[v + 3] = t.w;
    }

    float M = -INFINITY, Z = 0.0f;
    float acc[VEC];
#pragma unroll
    for (int v = 0; v < VEC; v++) acc[v] = 0.0f;

    int deg = d_deg[n];
    const int* cols = d_col + (size_t)n * CAP;

    for (int i = 4 * grp; i < deg; i += 8) {
        bool v1 = (i + 1 < deg), v2 = (i + 2 < deg), v3 = (i + 3 < deg);
        int m0 = cols[i];
        int m1 = cols[v1 ? i + 1 : i];
        int m2 = cols[v2 ? i + 2 : i];
        int m3 = cols[v3 ? i + 3 : i];

        float g0[VEC], g1[VEC], g2[VEC], g3[VEC];
        const float* p0p = hb + (size_t)m0 * D + k * VEC;
        const float* p1p = hb + (size_t)m1 * D + k * VEC;
        const float* p2p = hb + (size_t)m2 * D + k * VEC;
        const float* p3p = hb + (size_t)m3 * D + k * VEC;
#pragma unroll
        for (int v = 0; v < VEC; v += 4) {
            float4 t0 = *(const float4*)(p0p + v);
            float4 t1 = *(const float4*)(p1p + v);
            float4 t2 = *(const float4*)(p2p + v);
            float4 t3 = *(const float4*)(p3p + v);
            g0[v]=t0.x; g0[v+1]=t0.y; g0[v+2]=t0.z; g0[v+3]=t0.w;
            g1[v]=t1.x; g1[v+1]=t1.y; g1[v+2]=t1.z; g1[v+3]=t1.w;
            g2[v]=t2.x; g2[v+1]=t2.y; g2[v+2]=t2.z; g2[v+3]=t2.w;
            g3[v]=t3.x; g3[v+1]=t3.y; g3[v+2]=t3.z; g3[v+3]=t3.w;
        }

        float p0 = 0.f, p1 = 0.f, p2 = 0.f, p3 = 0.f;
#pragma unroll
        for (int v = 0; v < VEC; v++) {
            p0 = fmaf(f[v], g0[v], p0);
            p1 = fmaf(f[v], g1[v], p1);
            p2 = fmaf(f[v], g2[v], p2);
            p3 = fmaf(f[v], g3[v], p3);
        }
        // merged 4-way reduce within the 16-lane group
        float sA = (k & 8) ? p1 : p0;
        float tA = (k & 8) ? p0 : p1;
        sA += __shfl_xor_sync(gmask, tA, 8);
        float sB = (k & 8) ? p3 : p2;
        float tB = (k & 8) ? p2 : p3;
        sB += __shfl_xor_sync(gmask, tB, 8);
        float s  = (k & 4) ? sB : sA;
        float tt = (k & 4) ? sA : sB;
        s += __shfl_xor_sync(gmask, tt, 4);
        s += __shfl_xor_sync(gmask, s, 2);
        s += __shfl_xor_sync(gmask, s, 1);
        // layout: d0 @ +0, d2 @ +4, d1 @ +8, d3 @ +12
        float d0 = __shfl_sync(gmask, s, gbase + 0);
        float d2 = __shfl_sync(gmask, s, gbase + 4);
        float d1 = __shfl_sync(gmask, s, gbase + 8);
        float d3 = __shfl_sync(gmask, s, gbase + 12);
        if (!v1) d1 = -INFINITY;
        if (!v2) d2 = -INFINITY;
        if (!v3) d3 = -INFINITY;

        float bm   = fmaxf(fmaxf(d0, d1), fmaxf(d2, d3));
        float newM = fmaxf(M, bm);
        float sc   = __expf(M - newM);          // first batch: exp(-inf)=0
        float w0   = __expf(d0 - newM);
        float w1   = __expf(d1 - newM);
        float w2   = __expf(d2 - newM);
        float w3   = __expf(d3 - newM);
        Z = fmaf(Z, sc, (w0 + w1) + (w2 + w3));
#pragma unroll
        for (int v = 0; v < VEC; v++) {
            float a = acc[v] * sc;
            a = fmaf(w0, g0[v], a);
            a = fmaf(w1, g1[v], a);
            a = fmaf(w2, g2[v], a);
            a = fmaf(w3, g3[v], a);
            acc[v] = a;
        }
        M = newM;
    }

    // ---- merge the two groups' online-softmax states (flash combine) ----
    __syncwarp(FULL);
    float Mo   = __shfl_xor_sync(FULL, M, 16);
    float Zo   = __shfl_xor_sync(FULL, Z, 16);
    float newM = fmaxf(M, Mo);
    float sc   = __expf(M - newM);              // exp(-inf - x) = 0 handles empty group
    float sco  = __expf(Mo - newM);
    float Zt   = fmaf(Z, sc, Zo * sco);
    float inv  = 1.0f / fmaxf(Zt, 1e-30f);

    float* op = out + (size_t)row * D + k * VEC;
#pragma unroll
    for (int v = 0; v < VEC; v++) {
        float as  = acc[v] * sc;
        float atot = as + __shfl_xor_sync(FULL, as, 16);
        float o = fmaf(atot, inv, bias[k * VEC + v]);
        if (RELU) o = fmaxf(o, 0.0f);
        if (gbase == 0) op[v] = o;
    }
}

__global__ void __launch_bounds__(256, 4) agg1_kernel(const float* __restrict__ b1) {
    agg_body<DHID, true>(d_h1, b1, d_t1);
}
__global__ void __launch_bounds__(256, 4) agg2_kernel(const float* __restrict__ b2,
                                                      float* __restrict__ out) {
    agg_body<DOUT0, false>(d_h1, b2, out);      // h2 aliases d_h1
}

// ---------------- launch ------------------------------------------------------
extern "C" void kernel_launch(void* const* d_in, const int* in_sizes, int n_in,
                              void* d_out, int out_size) {
    const float* flow_x = (const float*)d_in[0];   // [B,N,64]
    const float* graph  = (const float*)d_in[1];   // [N,N]
    const float* W1     = (const float*)d_in[2];   // [128,64]
    const float* b1     = (const float*)d_in[3];   // [128]
    const float* W2     = (const float*)d_in[4];   // [64,128]
    const float* b2     = (const float*)d_in[5];   // [64]
    float*       outp   = (float*)d_out;           // [B,N,1,64]

    // 1) transpose weights
    prep_kernel<<<(DHID * DIN0 + 255) / 256, 256>>>(W1, W2);
    // 2) build CSR (shared by both layers & all batches)
    build_csr_kernel<<<NNODES / 8, 256>>>(graph);
    // 3) layer-1 linear: h1 = x @ W1^T
    lin1_kernel<<<BATCH * NNODES / 32, DHID>>>(flow_x);
    // 4) layer-1 sparse attention + bias + relu
    agg1_kernel<<<(BATCH * NNODES) / 8, 256>>>(b1);
    // 5) layer-2 linear: h2 = t1 @ W2^T  (h2 aliases d_h1)
    lin2_kernel<<<BATCH * NNODES / 32, DOUT0>>>();
    // 6) layer-2 sparse attention + bias -> final output
    agg2_kernel<<<(BATCH * NNODES) / 8, 256>>>(b2, outp);
}

// round 9
// speedup vs baseline: 1.0333x; 1.0333x over previous
#include <cuda_runtime.h>
#include <math.h>

// Problem constants
#define BATCH 8
#define NNODES 4096
#define DIN0 64
#define DHID 128
#define DOUT0 64
#define CAP 512          // max neighbors per row (mean ~82 at 2% density; P(>512)~0)

#define LOG2E 1.4426950408889634f

// ---------------- static device scratch (no allocations allowed) -------------
__device__ int   d_col[NNODES * CAP];            // 8 MB
__device__ int   d_deg[NNODES];
__device__ float d_h1[BATCH * NNODES * DHID];    // 16 MB (aliased for h2)
__device__ float d_t1[BATCH * NNODES * DHID];    // 16 MB
__device__ float d_wt1[DIN0 * DHID];             // W1^T  [k][c]
__device__ float d_wt2[DHID * DOUT0];            // W2^T  [k][c]

// ---------------- single-value warp sum (tail path) ---------------------------
__device__ __forceinline__ float warp_sum(float v) {
#pragma unroll
    for (int o = 16; o > 0; o >>= 1) v += __shfl_xor_sync(0xffffffffu, v, o);
    return v;
}

// ---------------- merged 4-way warp sum: 10 SHFLs for 4 reductions ------------
__device__ __forceinline__ void warp_sum4(float p0, float p1, float p2, float p3,
                                          float& d0, float& d1, float& d2, float& d3) {
    const unsigned FULL = 0xffffffffu;
    int lane = threadIdx.x & 31;
    float sA = (lane & 16) ? p1 : p0;
    float tA = (lane & 16) ? p0 : p1;
    sA += __shfl_xor_sync(FULL, tA, 16);
    float sB = (lane & 16) ? p3 : p2;
    float tB = (lane & 16) ? p2 : p3;
    sB += __shfl_xor_sync(FULL, tB, 16);
    float s = (lane & 8) ? sB : sA;
    float t = (lane & 8) ? sA : sB;
    s += __shfl_xor_sync(FULL, t, 8);
    s += __shfl_xor_sync(FULL, s, 4);
    s += __shfl_xor_sync(FULL, s, 2);
    s += __shfl_xor_sync(FULL, s, 1);
    d0 = __shfl_sync(FULL, s, 0);
    d2 = __shfl_sync(FULL, s, 8);
    d1 = __shfl_sync(FULL, s, 16);
    d3 = __shfl_sync(FULL, s, 24);
}

// ---------------- transpose W1, W2 into k-major layout -----------------------
__global__ void prep_kernel(const float* __restrict__ W1, const float* __restrict__ W2) {
    int i = blockIdx.x * blockDim.x + threadIdx.x;
    if (i < DHID * DIN0) {            // W1: [128][64] -> wt1[k*128 + c]
        int c = i / DIN0, k = i % DIN0;
        d_wt1[k * DHID + c] = W1[i];
    }
    if (i < DOUT0 * DHID) {           // W2: [64][128] -> wt2[k*64 + c]
        int c = i / DHID, k = i % DHID;
        d_wt2[k * DOUT0 + c] = W2[i];
    }
}

// ---------------- build CSR from dense binary graph (order-preserving) -------
__global__ void build_csr_kernel(const float* __restrict__ graph) {
    int row  = blockIdx.x * (blockDim.x >> 5) + (threadIdx.x >> 5);
    int lane = threadIdx.x & 31;
    if (row >= NNODES) return;
    const float* g = graph + (size_t)row * NNODES;
    int cnt = 0;
    for (int base = 0; base < NNODES; base += 32) {
        float v = g[base + lane];
        unsigned ball = __ballot_sync(0xffffffffu, v != 0.0f);
        int prefix = __popc(ball & ((1u << lane) - 1u));
        if (v != 0.0f) {
            int pos = cnt + prefix;
            if (pos < CAP) d_col[row * CAP + pos] = base + lane;
        }
        cnt += __popc(ball);
    }
    if (lane == 0) d_deg[row] = (cnt < CAP) ? cnt : CAP;
}

// ---------------- linear body: out[r][c] = sum_k x[r][k] * Wt[k][c] ----------
template <int DIN, int DOUT>
__device__ __forceinline__ void lin_body(const float* __restrict__ x,
                                         const float* __restrict__ wt,
                                         float* __restrict__ out) {
    constexpr int RPB = 32;
    __shared__ float xs[RPB * DIN];
    long base = (long)blockIdx.x * RPB;
    const float4* xg  = (const float4*)(x + base * DIN);
    float4*       xs4 = (float4*)xs;
    for (int i = threadIdx.x; i < RPB * DIN / 4; i += blockDim.x) xs4[i] = xg[i];
    __syncthreads();

    int c = threadIdx.x;   // blockDim == DOUT
    float acc[RPB];
#pragma unroll
    for (int r = 0; r < RPB; r++) acc[r] = 0.0f;

    for (int k = 0; k < DIN; k += 4) {
        float w0 = wt[(k + 0) * DOUT + c];
        float w1 = wt[(k + 1) * DOUT + c];
        float w2 = wt[(k + 2) * DOUT + c];
        float w3 = wt[(k + 3) * DOUT + c];
#pragma unroll
        for (int r = 0; r < RPB; r++) {
            float4 xv = *(const float4*)&xs[r * DIN + k];
            acc[r] = fmaf(xv.x, w0, fmaf(xv.y, w1, fmaf(xv.z, w2, fmaf(xv.w, w3, acc[r]))));
        }
    }
#pragma unroll
    for (int r = 0; r < RPB; r++) out[(base + r) * DOUT + c] = acc[r];
}

__global__ void lin1_kernel(const float* __restrict__ x) {
    lin_body<DIN0, DHID>(x, d_wt1, d_h1);
}
__global__ void lin2_kernel() {
    lin_body<DHID, DOUT0>(d_t1, d_wt2, d_h1);   // h2 aliases d_h1
}

// ---------------- sparse GAT aggregation: warp per (b, n) row ----------------
// 4-neighbor batched online softmax in exp2 domain; warp-uniform no-rescale
// fast path; 32-bit gather addressing; prefetched column indices.
template <int D, bool RELU>
__device__ __forceinline__ void agg_body(const float* __restrict__ h,
                                         const float* __restrict__ bias,
                                         float* __restrict__ out) {
    constexpr int VEC = D / 32;                  // 4 (agg1) or 2 (agg2)
    int warp = threadIdx.x >> 5;
    int lane = threadIdx.x & 31;
    long row = (long)blockIdx.x * (blockDim.x >> 5) + warp;   // row in [0, B*N)
    if (row >= (long)BATCH * NNODES) return;
    int n = (int)(row & (NNODES - 1));
    const float* hb = h + (size_t)(row - n) * D;   // batch base
    unsigned loff = (unsigned)lane * VEC;          // lane dim offset

    // own features, pre-scaled by log2(e): dots land in exp2 domain
    float f[VEC];
    if (VEC == 4) {
        float4 t = *(const float4*)(hb + ((unsigned)n * D + loff));
        f[0] = t.x * LOG2E; f[1] = t.y * LOG2E; f[2] = t.z * LOG2E; f[3] = t.w * LOG2E;
    } else {
        float2 t = *(const float2*)(hb + ((unsigned)n * D + loff));
        f[0] = t.x * LOG2E; f[1] = t.y * LOG2E;
    }

    float M = -INFINITY, Z = 0.0f;
    float acc[VEC];
#pragma unroll
    for (int v = 0; v < VEC; v++) acc[v] = 0.0f;

    int deg = d_deg[n];
    const int* cols = d_col + (size_t)n * CAP;   // 2KB-aligned row base

    int i = 0;
    int4 mm;
    if (deg >= 4) mm = *(const int4*)cols;
    // ---- batched main loop: 4 neighbors per iteration ----
    for (; i + 4 <= deg; i += 4) {
        int4 cur = mm;
        if (i + 8 <= deg) mm = *(const int4*)(cols + i + 4);   // prefetch

        float g0[VEC], g1[VEC], g2[VEC], g3[VEC];
        if (VEC == 4) {
            float4 t0 = *(const float4*)(hb + (((unsigned)cur.x << 7) + loff));
            float4 t1 = *(const float4*)(hb + (((unsigned)cur.y << 7) + loff));
            float4 t2 = *(const float4*)(hb + (((unsigned)cur.z << 7) + loff));
            float4 t3 = *(const float4*)(hb + (((unsigned)cur.w << 7) + loff));
            g0[0]=t0.x; g0[1]=t0.y; g0[2]=t0.z; g0[3]=t0.w;
            g1[0]=t1.x; g1[1]=t1.y; g1[2]=t1.z; g1[3]=t1.w;
            g2[0]=t2.x; g2[1]=t2.y; g2[2]=t2.z; g2[3]=t2.w;
            g3[0]=t3.x; g3[1]=t3.y; g3[2]=t3.z; g3[3]=t3.w;
        } else {
            float2 t0 = *(const float2*)(hb + (((unsigned)cur.x << 6) + loff));
            float2 t1 = *(const float2*)(hb + (((unsigned)cur.y << 6) + loff));
            float2 t2 = *(const float2*)(hb + (((unsigned)cur.z << 6) + loff));
            float2 t3 = *(const float2*)(hb + (((unsigned)cur.w << 6) + loff));
            g0[0]=t0.x; g0[1]=t0.y;  g1[0]=t1.x; g1[1]=t1.y;
            g2[0]=t2.x; g2[1]=t2.y;  g3[0]=t3.x; g3[1]=t3.y;
        }
        float p0 = 0.f, p1 = 0.f, p2 = 0.f, p3 = 0.f;
#pragma unroll
        for (int v = 0; v < VEC; v++) {
            p0 = fmaf(f[v], g0[v], p0);
            p1 = fmaf(f[v], g1[v], p1);
            p2 = fmaf(f[v], g2[v], p2);
            p3 = fmaf(f[v], g3[v], p3);
        }
        float d0, d1, d2, d3;
        warp_sum4(p0, p1, p2, p3, d0, d1, d2, d3);

        float bm = fmaxf(fmaxf(d0, d1), fmaxf(d2, d3));
        if (bm > M) {                        // warp-uniform; rare after warmup
            float sc = exp2f(M - bm);        // first batch: exp2(-inf)=0
            Z *= sc;
#pragma unroll
            for (int v = 0; v < VEC; v++) acc[v] *= sc;
            M = bm;
        }
        float w0 = exp2f(d0 - M);
        float w1 = exp2f(d1 - M);
        float w2 = exp2f(d2 - M);
        float w3 = exp2f(d3 - M);
        Z += (w0 + w1) + (w2 + w3);
#pragma unroll
        for (int v = 0; v < VEC; v++) {
            float a = acc[v];
            a = fmaf(w0, g0[v], a);
            a = fmaf(w1, g1[v], a);
            a = fmaf(w2, g2[v], a);
            a = fmaf(w3, g3[v], a);
            acc[v] = a;
        }
    }
    // ---- tail ----
    for (; i < deg; i++) {
        unsigned m = (unsigned)cols[i];
        float g[VEC];
        if (VEC == 4) {
            float4 t = *(const float4*)(hb + ((m << 7) + loff));
            g[0]=t.x; g[1]=t.y; g[2]=t.z; g[3]=t.w;
        } else {
            float2 t = *(const float2*)(hb + ((m << 6) + loff));
            g[0]=t.x; g[1]=t.y;
        }
        float p = 0.f;
#pragma unroll
        for (int v = 0; v < VEC; v++) p = fmaf(f[v], g[v], p);
        float dot = warp_sum(p);

        if (dot > M) {
            float sc = exp2f(M - dot);
            Z *= sc;
#pragma unroll
            for (int v = 0; v < VEC; v++) acc[v] *= sc;
            M = dot;
        }
        float w = exp2f(dot - M);
        Z += w;
#pragma unroll
        for (int v = 0; v < VEC; v++) acc[v] = fmaf(w, g[v], acc[v]);
    }

    float inv = 1.0f / fmaxf(Z, 1e-30f);   // deg>=1 via self-loop; guard anyway
    float* op = out + (size_t)row * D + loff;
#pragma unroll
    for (int v = 0; v < VEC; v++) {
        float o = fmaf(acc[v], inv, bias[loff + v]);
        if (RELU) o = fmaxf(o, 0.0f);
        op[v] = o;
    }
}

__global__ void agg1_kernel(const float* __restrict__ b1) {
    agg_body<DHID, true>(d_h1, b1, d_t1);
}
__global__ void agg2_kernel(const float* __restrict__ b2, float* __restrict__ out) {
    agg_body<DOUT0, false>(d_h1, b2, out);      // h2 aliases d_h1
}

// ---------------- launch ------------------------------------------------------
extern "C" void kernel_launch(void* const* d_in, const int* in_sizes, int n_in,
                              void* d_out, int out_size) {
    const float* flow_x = (const float*)d_in[0];   // [B,N,64]
    const float* graph  = (const float*)d_in[1];   // [N,N]
    const float* W1     = (const float*)d_in[2];   // [128,64]
    const float* b1     = (const float*)d_in[3];   // [128]
    const float* W2     = (const float*)d_in[4];   // [64,128]
    const float* b2     = (const float*)d_in[5];   // [64]
    float*       outp   = (float*)d_out;           // [B,N,1,64]

    // 1) transpose weights
    prep_kernel<<<(DHID * DIN0 + 255) / 256, 256>>>(W1, W2);
    // 2) build CSR (shared by both layers & all batches)
    build_csr_kernel<<<NNODES / 8, 256>>>(graph);
    // 3) layer-1 linear: h1 = x @ W1^T
    lin1_kernel<<<BATCH * NNODES / 32, DHID>>>(flow_x);
    // 4) layer-1 sparse attention + bias + relu
    agg1_kernel<<<(BATCH * NNODES) / 8, 256>>>(b1);
    // 5) layer-2 linear: h2 = t1 @ W2^T  (h2 aliases d_h1)
    lin2_kernel<<<BATCH * NNODES / 32, DOUT0>>>();
    // 6) layer-2 sparse attention + bias -> final output
    agg2_kernel<<<(BATCH * NNODES) / 8, 256>>>(b2, outp);
}

// round 10
// speedup vs baseline: 1.1713x; 1.1335x over previous
#include <cuda_runtime.h>
#include <math.h>

// Problem constants
#define BATCH 8
#define NNODES 4096
#define DIN0 64
#define DHID 128
#define DOUT0 64
#define CAP 512          // max neighbors per row (mean ~82 at 2% density; P(>512)~0)

#define LOG2E 1.4426950408889634f

// ---------------- static device scratch (no allocations allowed) -------------
// d_h1 aliasing: [0:2M) = y1 (layer1 score vecs), [2M:4M) = c (layer1 agg out);
// after y1 dies, [0:2M) is reused for h2 (layer2 linear out).
__device__ int   d_col[NNODES * CAP + 8];        // +8 pad: masked batch overread
__device__ int   d_deg[NNODES];
__device__ float d_h1[BATCH * NNODES * DHID];    // 16 MB, aliased as above
__device__ float d_t1[BATCH * NNODES * DHID];    // 16 MB
__device__ float d_wt1[DIN0 * DHID];             // W1^T  [k][c]
__device__ float d_wt2[DHID * DOUT0];            // W2^T  [k][c]
__device__ float d_g1[DIN0 * DIN0];              // G = W1^T W1 (64x64)

// ---------------- transpose W1, W2 into k-major layout -----------------------
__global__ void prep_kernel(const float* __restrict__ W1, const float* __restrict__ W2) {
    int i = blockIdx.x * blockDim.x + threadIdx.x;
    if (i < DHID * DIN0) {            // W1: [128][64] -> wt1[k*128 + c]
        int c = i / DIN0, k = i % DIN0;
        d_wt1[k * DHID + c] = W1[i];
    }
    if (i < DOUT0 * DHID) {           // W2: [64][128] -> wt2[k*64 + c]
        int c = i / DHID, k = i % DHID;
        d_wt2[k * DOUT0 + c] = W2[i];
    }
}

// ---------------- G = W1^T W1 : 64x64, contraction over 128 ------------------
__global__ void g1_kernel(const float* __restrict__ W1) {
    int i = blockIdx.x * blockDim.x + threadIdx.x;   // 4096 threads
    int d = i & 63, e = i >> 6;
    float s = 0.0f;
#pragma unroll 4
    for (int h = 0; h < DHID; h++)
        s = fmaf(W1[h * DIN0 + d], W1[h * DIN0 + e], s);
    d_g1[e * DIN0 + d] = s;
}

// ---------------- build CSR from dense binary graph (order-preserving) -------
__global__ void build_csr_kernel(const float* __restrict__ graph) {
    int row  = blockIdx.x * (blockDim.x >> 5) + (threadIdx.x >> 5);
    int lane = threadIdx.x & 31;
    if (row >= NNODES) return;
    const float* g = graph + (size_t)row * NNODES;
    int cnt = 0;
    for (int base = 0; base < NNODES; base += 32) {
        float v = g[base + lane];
        unsigned ball = __ballot_sync(0xffffffffu, v != 0.0f);
        int prefix = __popc(ball & ((1u << lane) - 1u));
        if (v != 0.0f) {
            int pos = cnt + prefix;
            if (pos < CAP) d_col[row * CAP + pos] = base + lane;
        }
        cnt += __popc(ball);
    }
    if (lane == 0) d_deg[row] = (cnt < CAP) ? cnt : CAP;
}

// ---------------- linear body: out[r][c] = sum_k x[r][k]*Wt[k][c] (+b, relu) -
template <int DIN, int DOUT, bool HAS_BIAS, bool RELU>
__device__ __forceinline__ void lin_body(const float* __restrict__ x,
                                         const float* __restrict__ wt,
                                         const float* __restrict__ bias,
                                         float* __restrict__ out) {
    constexpr int RPB = 32;
    __shared__ float xs[RPB * DIN];
    long base = (long)blockIdx.x * RPB;
    const float4* xg  = (const float4*)(x + base * DIN);
    float4*       xs4 = (float4*)xs;
    for (int i = threadIdx.x; i < RPB * DIN / 4; i += blockDim.x) xs4[i] = xg[i];
    __syncthreads();

    int c = threadIdx.x;   // blockDim == DOUT
    float b = HAS_BIAS ? bias[c] : 0.0f;
    float acc[RPB];
#pragma unroll
    for (int r = 0; r < RPB; r++) acc[r] = 0.0f;

    for (int k = 0; k < DIN; k += 4) {
        float w0 = wt[(k + 0) * DOUT + c];
        float w1 = wt[(k + 1) * DOUT + c];
        float w2 = wt[(k + 2) * DOUT + c];
        float w3 = wt[(k + 3) * DOUT + c];
#pragma unroll
        for (int r = 0; r < RPB; r++) {
            float4 xv = *(const float4*)&xs[r * DIN + k];
            acc[r] = fmaf(xv.x, w0, fmaf(xv.y, w1, fmaf(xv.z, w2, fmaf(xv.w, w3, acc[r]))));
        }
    }
#pragma unroll
    for (int r = 0; r < RPB; r++) {
        float o = acc[r] + b;
        if (RELU) o = fmaxf(o, 0.0f);
        out[(base + r) * DOUT + c] = o;
    }
}

__global__ void y1_kernel(const float* __restrict__ x) {          // y1 = x @ G
    lin_body<DIN0, DIN0, false, false>(x, d_g1, nullptr, d_h1);
}
__global__ void postlin_kernel(const float* __restrict__ b1) {    // t1 = relu(c@W1^T+b1)
    lin_body<DIN0, DHID, true, true>(d_h1 + BATCH * NNODES * DIN0, d_wt1, b1, d_t1);
}
__global__ void lin2_kernel() {                                   // h2 = t1 @ W2^T
    lin_body<DHID, DOUT0, false, false>(d_t1, d_wt2, nullptr, d_h1);
}

// ---------------- 8-neighbor batch: load, dot, merged reduce, softmax update -
template <bool MASKED>
__device__ __forceinline__ void agg_batch(const int* __restrict__ cols, int i, int rem,
                                          const float* __restrict__ hb, unsigned loff,
                                          float f0, float f1,
                                          float& M, float& Z, float& a0, float& a1) {
    const unsigned FULL = 0xffffffffu;
    int lane = threadIdx.x & 31;
    int4 ca = *(const int4*)(cols + i);
    int4 cb = *(const int4*)(cols + i + 4);
    float2 g0 = *(const float2*)(hb + (((unsigned)ca.x << 6) + loff));
    float2 g1 = *(const float2*)(hb + (((unsigned)ca.y << 6) + loff));
    float2 g2 = *(const float2*)(hb + (((unsigned)ca.z << 6) + loff));
    float2 g3 = *(const float2*)(hb + (((unsigned)ca.w << 6) + loff));
    float2 g4 = *(const float2*)(hb + (((unsigned)cb.x << 6) + loff));
    float2 g5 = *(const float2*)(hb + (((unsigned)cb.y << 6) + loff));
    float2 g6 = *(const float2*)(hb + (((unsigned)cb.z << 6) + loff));
    float2 g7 = *(const float2*)(hb + (((unsigned)cb.w << 6) + loff));

    float p0 = fmaf(f0, g0.x, f1 * g0.y);
    float p1 = fmaf(f0, g1.x, f1 * g1.y);
    float p2 = fmaf(f0, g2.x, f1 * g2.y);
    float p3 = fmaf(f0, g3.x, f1 * g3.y);
    float p4 = fmaf(f0, g4.x, f1 * g4.y);
    float p5 = fmaf(f0, g5.x, f1 * g5.y);
    float p6 = fmaf(f0, g6.x, f1 * g6.y);
    float p7 = fmaf(f0, g7.x, f1 * g7.y);

    // merged 8-way warp reduction: 9 SHFL-chain + 8 broadcasts = 17 SHFLs
    float qA = (lane & 16) ? p1 : p0, tA = (lane & 16) ? p0 : p1;
    qA += __shfl_xor_sync(FULL, tA, 16);
    float qB = (lane & 16) ? p3 : p2, tB = (lane & 16) ? p2 : p3;
    qB += __shfl_xor_sync(FULL, tB, 16);
    float qC = (lane & 16) ? p5 : p4, tC = (lane & 16) ? p4 : p5;
    qC += __shfl_xor_sync(FULL, tC, 16);
    float qD = (lane & 16) ? p7 : p6, tD = (lane & 16) ? p6 : p7;
    qD += __shfl_xor_sync(FULL, tD, 16);
    float rA = (lane & 8) ? qB : qA, rAt = (lane & 8) ? qA : qB;
    rA += __shfl_xor_sync(FULL, rAt, 8);
    float rB = (lane & 8) ? qD : qC, rBt = (lane & 8) ? qC : qD;
    rB += __shfl_xor_sync(FULL, rBt, 8);
    float u = (lane & 4) ? rB : rA, ut = (lane & 4) ? rA : rB;
    u += __shfl_xor_sync(FULL, ut, 4);
    u += __shfl_xor_sync(FULL, u, 2);
    u += __shfl_xor_sync(FULL, u, 1);
    // group-of-4 ownership: 0:p0 4:p4 8:p2 12:p6 16:p1 20:p5 24:p3 28:p7
    float d0 = __shfl_sync(FULL, u, 0);
    float d1 = __shfl_sync(FULL, u, 16);
    float d2 = __shfl_sync(FULL, u, 8);
    float d3 = __shfl_sync(FULL, u, 24);
    float d4 = __shfl_sync(FULL, u, 4);
    float d5 = __shfl_sync(FULL, u, 20);
    float d6 = __shfl_sync(FULL, u, 12);
    float d7 = __shfl_sync(FULL, u, 28);

    if (MASKED) {                       // only last batch; rem >= 1
        if (rem < 2) d1 = -INFINITY;
        if (rem < 3) d2 = -INFINITY;
        if (rem < 4) d3 = -INFINITY;
        if (rem < 5) d4 = -INFINITY;
        if (rem < 6) d5 = -INFINITY;
        if (rem < 7) d6 = -INFINITY;
        if (rem < 8) d7 = -INFINITY;
    }

    float bm = fmaxf(fmaxf(fmaxf(d0, d1), fmaxf(d2, d3)),
                     fmaxf(fmaxf(d4, d5), fmaxf(d6, d7)));
    if (bm > M) {                        // warp-uniform; rare after warmup
        float sc = exp2f(M - bm);        // first batch: exp2(-inf)=0
        Z *= sc; a0 *= sc; a1 *= sc;
        M = bm;
    }
    float w0 = exp2f(d0 - M);
    float w1 = exp2f(d1 - M);
    float w2 = exp2f(d2 - M);
    float w3 = exp2f(d3 - M);
    float w4 = exp2f(d4 - M);
    float w5 = exp2f(d5 - M);
    float w6 = exp2f(d6 - M);
    float w7 = exp2f(d7 - M);
    Z += ((w0 + w1) + (w2 + w3)) + ((w4 + w5) + (w6 + w7));
    a0 = fmaf(w0, g0.x, a0); a1 = fmaf(w0, g0.y, a1);
    a0 = fmaf(w1, g1.x, a0); a1 = fmaf(w1, g1.y, a1);
    a0 = fmaf(w2, g2.x, a0); a1 = fmaf(w2, g2.y, a1);
    a0 = fmaf(w3, g3.x, a0); a1 = fmaf(w3, g3.y, a1);
    a0 = fmaf(w4, g4.x, a0); a1 = fmaf(w4, g4.y, a1);
    a0 = fmaf(w5, g5.x, a0); a1 = fmaf(w5, g5.y, a1);
    a0 = fmaf(w6, g6.x, a0); a1 = fmaf(w6, g6.y, a1);
    a0 = fmaf(w7, g7.x, a0); a1 = fmaf(w7, g7.y, a1);
}

// ---------------- sparse GAT aggregation (D=64): warp per (b,n) row ----------
// score_nm = fsrc[row] . gsrc[b,m]  (fsrc pre-scaled to exp2 domain here)
// out[row] = softmax-weighted sum of gsrc[b,m] (+bias)
template <bool HAS_BIAS, bool RELU>
__device__ __forceinline__ void agg_body64(const float* __restrict__ fsrc,
                                           const float* __restrict__ gsrc,
                                           const float* __restrict__ bias,
                                           float* __restrict__ out) {
    int warp = threadIdx.x >> 5;
    int lane = threadIdx.x & 31;
    int row = blockIdx.x * 8 + warp;                 // grid exact: B*N/8 blocks
    int n = row & (NNODES - 1);
    const float* hb = gsrc + ((size_t)(row - n) << 6);   // batch base (64-dim rows)
    unsigned loff = (unsigned)lane * 2;

    float2 ft = *(const float2*)(fsrc + ((size_t)row << 6) + loff);
    float f0 = ft.x * LOG2E, f1 = ft.y * LOG2E;      // exp2-domain scores

    float M = -INFINITY, Z = 0.0f, a0 = 0.0f, a1 = 0.0f;
    int deg = d_deg[n];
    const int* cols = d_col + n * CAP;

    int i = 0;
    for (; i + 8 <= deg; i += 8)
        agg_batch<false>(cols, i, 8, hb, loff, f0, f1, M, Z, a0, a1);
    if (i < deg)
        agg_batch<true>(cols, i, deg - i, hb, loff, f0, f1, M, Z, a0, a1);

    float inv = 1.0f / Z;                            // Z >= 1 (max weight = 1)
    float o0 = a0 * inv, o1 = a1 * inv;
    if (HAS_BIAS) { o0 += bias[loff]; o1 += bias[loff + 1]; }
    if (RELU)     { o0 = fmaxf(o0, 0.0f); o1 = fmaxf(o1, 0.0f); }
    *(float2*)(out + ((size_t)row << 6) + loff) = make_float2(o0, o1);
}

__global__ void agg1_kernel(const float* __restrict__ x) {
    // scores via y1 = x G (fsrc = d_h1[0:2M)); values = x; out = c (d_h1[2M:4M))
    agg_body64<false, false>(d_h1, x, nullptr, d_h1 + BATCH * NNODES * DIN0);
}
__global__ void agg2_kernel(const float* __restrict__ b2, float* __restrict__ out) {
    // scores and values both h2 (d_h1[0:2M), written by lin2)
    agg_body64<true, false>(d_h1, d_h1, b2, out);
}

// ---------------- launch ------------------------------------------------------
extern "C" void kernel_launch(void* const* d_in, const int* in_sizes, int n_in,
                              void* d_out, int out_size) {
    const float* flow_x = (const float*)d_in[0];   // [B,N,64]
    const float* graph  = (const float*)d_in[1];   // [N,N]
    const float* W1     = (const float*)d_in[2];   // [128,64]
    const float* b1     = (const float*)d_in[3];   // [128]
    const float* W2     = (const float*)d_in[4];   // [64,128]
    const float* b2     = (const float*)d_in[5];   // [64]
    float*       outp   = (float*)d_out;           // [B,N,1,64]

    // 1) weight transposes + G = W1^T W1
    prep_kernel<<<(DHID * DIN0 + 255) / 256, 256>>>(W1, W2);
    g1_kernel<<<DIN0 * DIN0 / 256, 256>>>(W1);
    // 2) build CSR (shared by both layers & all batches)
    build_csr_kernel<<<NNODES / 8, 256>>>(graph);
    // 3) y1 = x @ G  (64-dim score vectors for layer 1)
    y1_kernel<<<BATCH * NNODES / 32, DIN0>>>(flow_x);
    // 4) layer-1 sparse attention in input space: c = softmax(y1.x) @ x
    agg1_kernel<<<(BATCH * NNODES) / 8, 256>>>(flow_x);
    // 5) t1 = relu(c @ W1^T + b1)
    postlin_kernel<<<BATCH * NNODES / 32, DHID>>>(b1);
    // 6) h2 = t1 @ W2^T
    lin2_kernel<<<BATCH * NNODES / 32, DOUT0>>>();
    // 7) layer-2 sparse attention + bias -> final output
    agg2_kernel<<<(BATCH * NNODES) / 8, 256>>>(b2, outp);
}